// round 13
// baseline (speedup 1.0000x reference)
#include <cuda_runtime.h>
#include <cuda_bf16.h>
#include <stdint.h>
#include <math.h>

// ============================================================================
// Problem constants
// ============================================================================
#define BATCH 8
#define SEQ   2048
#define DM    512
#define MTOT  (BATCH * SEQ)   // 16384

// ============================================================================
// Device global scratch (bf16 hi/lo pairs + fp32 scores)
// ============================================================================
__device__ __nv_bfloat16 g_xh[MTOT * DM],  g_xl[MTOT * DM];
__device__ __nv_bfloat16 g_Wth[3][DM * DM], g_Wtl[3][DM * DM];   // transposed W: [n][k]
__device__ __nv_bfloat16 g_Qh[MTOT * DM],  g_Ql[MTOT * DM];
__device__ __nv_bfloat16 g_Kh[MTOT * DM],  g_Kl[MTOT * DM];
__device__ __nv_bfloat16 g_Vth[MTOT * DM], g_Vtl[MTOT * DM];     // transposed V: [b][d][s]
__device__ float         g_S [(size_t)BATCH * SEQ * SEQ];
__device__ __nv_bfloat16 g_Ph[(size_t)BATCH * SEQ * SEQ];
__device__ __nv_bfloat16 g_Pl[(size_t)BATCH * SEQ * SEQ];

// ============================================================================
// PTX helpers (sm_80-level: ldmatrix / mma.sync / cp.async — no 'a' features)
// ============================================================================
__device__ __forceinline__ uint32_t smem_to_u32(const void* p) {
    uint32_t a;
    asm("{ .reg .u64 t; cvta.to.shared.u64 t, %1; cvt.u32.u64 %0, t; }"
        : "=r"(a) : "l"(p));
    return a;
}

__device__ __forceinline__ void cp_async16(uint32_t dst, const void* src) {
    asm volatile("cp.async.cg.shared.global [%0], [%1], 16;"
                 :: "r"(dst), "l"(__cvta_generic_to_global(src)));
}
#define CP_COMMIT() asm volatile("cp.async.commit_group;" ::: "memory")
#define CP_WAIT(n)  asm volatile("cp.async.wait_group %0;" :: "n"(n) : "memory")

__device__ __forceinline__ void ldsm4(uint32_t* r, uint32_t addr) {
    asm volatile("ldmatrix.sync.aligned.m8n8.x4.shared.b16 {%0,%1,%2,%3}, [%4];"
                 : "=r"(r[0]), "=r"(r[1]), "=r"(r[2]), "=r"(r[3]) : "r"(addr));
}

__device__ __forceinline__ void mma_bf16(float* c, const uint32_t* a,
                                         uint32_t b0, uint32_t b1) {
    asm volatile(
        "mma.sync.aligned.m16n8k16.row.col.f32.bf16.bf16.f32 "
        "{%0,%1,%2,%3}, {%4,%5,%6,%7}, {%8,%9}, {%0,%1,%2,%3};"
        : "+f"(c[0]), "+f"(c[1]), "+f"(c[2]), "+f"(c[3])
        : "r"(a[0]), "r"(a[1]), "r"(a[2]), "r"(a[3]), "r"(b0), "r"(b1));
}

__device__ __forceinline__ void split_f32(float v, __nv_bfloat16& h, __nv_bfloat16& l) {
    h = __float2bfloat16(v);
    l = __float2bfloat16(v - __bfloat162float(h));
}

// ============================================================================
// SMEM: CTA tile 128(M) x 256(N), BK=64. Per stage: Ah, Al (128x64 each),
// Bh, Bl (256x64 each). Rows = 128B data + 16B pad = 144B (conflict-free for
// ldmatrix: bank = (36r + w) mod 32 -> 4r distinct over 8 rows).
// 2 stages, single __syncthreads per iteration.
// ============================================================================
#define PADB      144
#define TILE_A    (128 * PADB)                 // 18432 B
#define TILE_B    (256 * PADB)                 // 36864 B
#define STAGE_SM  (2 * TILE_A + 2 * TILE_B)    // 110592 B
#define NSTAGE    2
#define SMEM_TOTAL (NSTAGE * STAGE_SM)         // 221184 B

// ============================================================================
// Core GEMM tile body: C = A * B^T  (A[M][K], B[N][K], K-contiguous),
// 3-term bf16 split on mma.sync tensor cores.
// 8 warps: 2(M) x 4(N); warp tile 64x64; per-thread acc[4][8][4].
// Split terms are issued term-major so same-accumulator MMAs are 32 apart.
//   EPI 0: write bf16 hi/lo row-major (out0/out1, ldC)
//   EPI 1: write bf16 hi/lo transposed (Vt[b][n][s]; batch derived from m row)
//   EPI 2: write fp32 row-major scaled by alpha
// ============================================================================
template <int EPI>
__device__ __forceinline__ void gemm_body(
    const __nv_bfloat16* __restrict__ Ah, const __nv_bfloat16* __restrict__ Al,
    const __nv_bfloat16* __restrict__ Bh, const __nv_bfloat16* __restrict__ Bl,
    void* out0, void* out1, int K, long ldA, long ldB, int ldC, float alpha)
{
    extern __shared__ char smem[];
    const uint32_t sb = smem_to_u32(smem);
    const int tid  = threadIdx.x;
    const int wid  = tid >> 5;
    const int lane = tid & 31;
    const int rowBlock = blockIdx.y * 128;
    const int colBlock = blockIdx.x * 256;
    const int wm = (wid >> 2) * 64;   // warp M offset (2 warps in M)
    const int wn = (wid & 3) * 64;    // warp N offset (4 warps in N)

    float acc[4][8][4];
#pragma unroll
    for (int mt = 0; mt < 4; mt++)
#pragma unroll
        for (int nt = 0; nt < 8; nt++)
#pragma unroll
            for (int e = 0; e < 4; e++) acc[mt][nt][e] = 0.0f;

    const __nv_bfloat16* srcA_h = Ah + (long)rowBlock * ldA;
    const __nv_bfloat16* srcA_l = Al + (long)rowBlock * ldA;
    const __nv_bfloat16* srcB_h = Bh + (long)colBlock * ldB;
    const __nv_bfloat16* srcB_l = Bl + (long)colBlock * ldB;

    // Staging (BK=64: rows of 128B = 8 x 16B chunks).
    // A tiles: 1024 chunks -> 4/thread; B tiles: 2048 chunks -> 8/thread.
    auto prefetch = [&](int chunk, int stage) {
        const long k0 = (long)chunk * 64;
        const uint32_t s0 = sb + stage * STAGE_SM;
#pragma unroll
        for (int j = 0; j < 4; j++) {
            const int t = tid + j * 256;
            const int r = t >> 3, c = t & 7;
            cp_async16(s0 + r * PADB + c * 16,          srcA_h + (long)r * ldA + k0 + c * 8);
            cp_async16(s0 + TILE_A + r * PADB + c * 16, srcA_l + (long)r * ldA + k0 + c * 8);
        }
#pragma unroll
        for (int j = 0; j < 8; j++) {
            const int t = tid + j * 256;
            const int r = t >> 3, c = t & 7;
            cp_async16(s0 + 2 * TILE_A + r * PADB + c * 16,
                       srcB_h + (long)r * ldB + k0 + c * 8);
            cp_async16(s0 + 2 * TILE_A + TILE_B + r * PADB + c * 16,
                       srcB_l + (long)r * ldB + k0 + c * 8);
        }
        CP_COMMIT();
    };

    const int NIT = K / 64;
    prefetch(0, 0);

    // ldmatrix address components within a stage.
    // A x4: lanes 0-15 -> rows m0..15 @ k0; lanes 16-31 -> same rows @ k8.
    const uint32_t aRow = (uint32_t)(wm + (lane & 15)) * PADB + ((lane >> 4) * 16);
    // B x4: lanes 0-7: n0-7@k0, 8-15: n0-7@k8, 16-23: n8-15@k0, 24-31: n8-15@k8.
    const uint32_t bRow = (uint32_t)(wn + ((lane >> 4) << 3) + (lane & 7)) * PADB
                        + (((lane >> 3) & 1) * 16);

    for (int i = 0; i < NIT; i++) {
        CP_WAIT(0);
        __syncthreads();
        // Prefetch chunk i+1 into the opposite stage: its readers (iter i-1)
        // all passed the barrier above, so overwrite is safe. The cp.async
        // flies during this iteration's compute; CP_WAIT(0) drains it at the
        // top of iteration i+1.
        if (i + 1 < NIT) prefetch(i + 1, (i + 1) & 1);

        const uint32_t s0 = sb + (i & 1) * STAGE_SM;
        const uint32_t aBaseH = s0 + aRow;
        const uint32_t aBaseL = s0 + TILE_A + aRow;
        const uint32_t bBaseH = s0 + 2 * TILE_A + bRow;
        const uint32_t bBaseL = s0 + 2 * TILE_A + TILE_B + bRow;

#pragma unroll
        for (int ks = 0; ks < 4; ks++) {
            const uint32_t ko = ks * 32;            // 16 bf16 = 32 B
            uint32_t ah[4][4], al[4][4], bh[4][4], bl[4][4];
#pragma unroll
            for (int mt = 0; mt < 4; mt++) {
                ldsm4(ah[mt], aBaseH + mt * (16 * PADB) + ko);
                ldsm4(al[mt], aBaseL + mt * (16 * PADB) + ko);
            }
#pragma unroll
            for (int np = 0; np < 4; np++) {
                ldsm4(bh[np], bBaseH + np * (16 * PADB) + ko);
                ldsm4(bl[np], bBaseL + np * (16 * PADB) + ko);
            }
            // Term-major issue order: reuse of any acc register is 32
            // independent MMAs apart (no HMMA acc-RAW stalls).
#pragma unroll
            for (int mt = 0; mt < 4; mt++)
#pragma unroll
                for (int np = 0; np < 4; np++) {
                    mma_bf16(acc[mt][2 * np + 0], ah[mt], bh[np][0], bh[np][1]);
                    mma_bf16(acc[mt][2 * np + 1], ah[mt], bh[np][2], bh[np][3]);
                }
#pragma unroll
            for (int mt = 0; mt < 4; mt++)
#pragma unroll
                for (int np = 0; np < 4; np++) {
                    mma_bf16(acc[mt][2 * np + 0], ah[mt], bl[np][0], bl[np][1]);
                    mma_bf16(acc[mt][2 * np + 1], ah[mt], bl[np][2], bl[np][3]);
                }
#pragma unroll
            for (int mt = 0; mt < 4; mt++)
#pragma unroll
                for (int np = 0; np < 4; np++) {
                    mma_bf16(acc[mt][2 * np + 0], al[mt], bh[np][0], bh[np][1]);
                    mma_bf16(acc[mt][2 * np + 1], al[mt], bh[np][2], bh[np][3]);
                }
        }
    }

    // ------------------------------------------------------------------ epilogue
    const int mBase = rowBlock + wm + (lane >> 2);
    const int nBase = colBlock + wn + 2 * (lane & 3);
#pragma unroll
    for (int mt = 0; mt < 4; mt++) {
#pragma unroll
        for (int nt = 0; nt < 8; nt++) {
            const int m0 = mBase + mt * 16;
            const int n  = nBase + nt * 8;
            const float v00 = acc[mt][nt][0], v01 = acc[mt][nt][1];
            const float v10 = acc[mt][nt][2], v11 = acc[mt][nt][3];

            if (EPI == 2) {
                float* C = (float*)out0;
                *(float2*)(C + (long)m0 * ldC + n)       = make_float2(v00 * alpha, v01 * alpha);
                *(float2*)(C + (long)(m0 + 8) * ldC + n) = make_float2(v10 * alpha, v11 * alpha);
            } else if (EPI == 0) {
                __nv_bfloat16* H = (__nv_bfloat16*)out0;
                __nv_bfloat16* L = (__nv_bfloat16*)out1;
                __nv_bfloat16 h0, l0, h1, l1;
                split_f32(v00, h0, l0); split_f32(v01, h1, l1);
                *(__nv_bfloat162*)(H + (long)m0 * ldC + n) = __nv_bfloat162(h0, h1);
                *(__nv_bfloat162*)(L + (long)m0 * ldC + n) = __nv_bfloat162(l0, l1);
                split_f32(v10, h0, l0); split_f32(v11, h1, l1);
                *(__nv_bfloat162*)(H + (long)(m0 + 8) * ldC + n) = __nv_bfloat162(h0, h1);
                *(__nv_bfloat162*)(L + (long)(m0 + 8) * ldC + n) = __nv_bfloat162(l0, l1);
            } else {  // EPI == 1: transposed store Vt[b][n][s]
                __nv_bfloat16* H = (__nv_bfloat16*)out0;
                __nv_bfloat16* L = (__nv_bfloat16*)out1;
#pragma unroll
                for (int rr = 0; rr < 2; rr++) {
                    const int m = m0 + rr * 8;
                    const int bb = m >> 11;
                    const int s  = m & 2047;
                    const float va = (rr == 0) ? v00 : v10;
                    const float vb = (rr == 0) ? v01 : v11;
                    __nv_bfloat16 h, l;
                    split_f32(va, h, l);
                    H[((long)bb * DM + n) * SEQ + s] = h;
                    L[((long)bb * DM + n) * SEQ + s] = l;
                    split_f32(vb, h, l);
                    H[((long)bb * DM + n + 1) * SEQ + s] = h;
                    L[((long)bb * DM + n + 1) * SEQ + s] = l;
                }
            }
        }
    }
}

// ---------------------------------------------------------------------------
// GEMM kernels
// ---------------------------------------------------------------------------
__global__ __launch_bounds__(256, 1) void tc_gemm_qkv() {
    const int z = blockIdx.z;
    const __nv_bfloat16* Bh = g_Wth[z];
    const __nv_bfloat16* Bl = g_Wtl[z];
    if (z == 2) {
        gemm_body<1>(g_xh, g_xl, Bh, Bl, g_Vth, g_Vtl, DM, DM, DM, 0, 1.0f);
    } else if (z == 1) {
        gemm_body<0>(g_xh, g_xl, Bh, Bl, g_Kh, g_Kl, DM, DM, DM, DM, 1.0f);
    } else {
        gemm_body<0>(g_xh, g_xl, Bh, Bl, g_Qh, g_Ql, DM, DM, DM, DM, 1.0f);
    }
}

__global__ __launch_bounds__(256, 1) void tc_gemm_scores(float alpha) {
    const long z = blockIdx.z;
    const long sQ = (long)SEQ * DM;
    gemm_body<2>(g_Qh + z * sQ, g_Ql + z * sQ, g_Kh + z * sQ, g_Kl + z * sQ,
                 g_S + z * (long)SEQ * SEQ, nullptr, DM, DM, DM, SEQ, alpha);
}

__global__ __launch_bounds__(256, 1) void tc_gemm_pv(float* out) {
    const long z = blockIdx.z;
    gemm_body<2>(g_Ph + z * (long)SEQ * SEQ, g_Pl + z * (long)SEQ * SEQ,
                 g_Vth + z * (long)DM * SEQ, g_Vtl + z * (long)DM * SEQ,
                 out + z * (long)SEQ * DM, nullptr, SEQ, SEQ, SEQ, DM, 1.0f);
}

// ---------------------------------------------------------------------------
// Conversion kernels
// ---------------------------------------------------------------------------
__global__ __launch_bounds__(256) void convert_x_kernel(const float* __restrict__ x) {
    const long i4 = (long)(blockIdx.x * 256 + threadIdx.x) * 4;
    if (i4 >= (long)MTOT * DM) return;
    float4 v = *(const float4*)(x + i4);
    __nv_bfloat16 h0, l0, h1, l1, h2, l2, h3, l3;
    split_f32(v.x, h0, l0); split_f32(v.y, h1, l1);
    split_f32(v.z, h2, l2); split_f32(v.w, h3, l3);
    *(__nv_bfloat162*)(g_xh + i4)     = __nv_bfloat162(h0, h1);
    *(__nv_bfloat162*)(g_xh + i4 + 2) = __nv_bfloat162(h2, h3);
    *(__nv_bfloat162*)(g_xl + i4)     = __nv_bfloat162(l0, l1);
    *(__nv_bfloat162*)(g_xl + i4 + 2) = __nv_bfloat162(l2, l3);
}

__global__ __launch_bounds__(256) void convert_w_kernel(
    const float* __restrict__ WQ, const float* __restrict__ WK,
    const float* __restrict__ WV)
{
    const int idx = blockIdx.x * 256 + threadIdx.x;
    if (idx >= 3 * DM * DM) return;
    const int w = idx / (DM * DM);
    const int rem = idx - w * DM * DM;
    const int k = rem / DM, n = rem % DM;
    const float* src = (w == 0) ? WQ : (w == 1) ? WK : WV;
    __nv_bfloat16 h, l;
    split_f32(src[k * DM + n], h, l);
    g_Wth[w][n * DM + k] = h;      // transposed: [n][k]
    g_Wtl[w][n * DM + k] = l;
}

// ---------------------------------------------------------------------------
// Softmax: fp32 scores row -> bf16 hi/lo probability row
// ---------------------------------------------------------------------------
__global__ __launch_bounds__(256) void softmax_kernel() {
    const size_t rowoff = (size_t)blockIdx.x * SEQ;
    const float* row = g_S + rowoff;
    const int tid = threadIdx.x;

    float4 v[2];
    v[0] = *(const float4*)(row + tid * 4);
    v[1] = *(const float4*)(row + 1024 + tid * 4);

    __shared__ float red[8];

    float m = fmaxf(fmaxf(fmaxf(v[0].x, v[0].y), fmaxf(v[0].z, v[0].w)),
                    fmaxf(fmaxf(v[1].x, v[1].y), fmaxf(v[1].z, v[1].w)));
#pragma unroll
    for (int o = 16; o > 0; o >>= 1) m = fmaxf(m, __shfl_xor_sync(0xffffffffu, m, o));
    if ((tid & 31) == 0) red[tid >> 5] = m;
    __syncthreads();
    if (tid < 8) {
        float t = red[tid];
#pragma unroll
        for (int o = 4; o > 0; o >>= 1) t = fmaxf(t, __shfl_xor_sync(0xffu, t, o));
        if (tid == 0) red[0] = t;
    }
    __syncthreads();
    m = red[0];
    __syncthreads();

    float s = 0.0f;
#pragma unroll
    for (int i = 0; i < 2; i++) {
        v[i].x = expf(v[i].x - m); s += v[i].x;
        v[i].y = expf(v[i].y - m); s += v[i].y;
        v[i].z = expf(v[i].z - m); s += v[i].z;
        v[i].w = expf(v[i].w - m); s += v[i].w;
    }
#pragma unroll
    for (int o = 16; o > 0; o >>= 1) s += __shfl_xor_sync(0xffffffffu, s, o);
    if ((tid & 31) == 0) red[tid >> 5] = s;
    __syncthreads();
    if (tid < 8) {
        float t = red[tid];
#pragma unroll
        for (int o = 4; o > 0; o >>= 1) t += __shfl_xor_sync(0xffu, t, o);
        if (tid == 0) red[0] = t;
    }
    __syncthreads();
    const float inv = 1.0f / red[0];

    __nv_bfloat16* Ph = g_Ph + rowoff;
    __nv_bfloat16* Pl = g_Pl + rowoff;
#pragma unroll
    for (int i = 0; i < 2; i++) {
        const int base = i * 1024 + tid * 4;
        __nv_bfloat16 h0, l0, h1, l1, h2, l2, h3, l3;
        split_f32(v[i].x * inv, h0, l0);
        split_f32(v[i].y * inv, h1, l1);
        split_f32(v[i].z * inv, h2, l2);
        split_f32(v[i].w * inv, h3, l3);
        *(__nv_bfloat162*)(Ph + base)     = __nv_bfloat162(h0, h1);
        *(__nv_bfloat162*)(Ph + base + 2) = __nv_bfloat162(h2, h3);
        *(__nv_bfloat162*)(Pl + base)     = __nv_bfloat162(l0, l1);
        *(__nv_bfloat162*)(Pl + base + 2) = __nv_bfloat162(l2, l3);
    }
}

// ---------------------------------------------------------------------------
extern "C" void kernel_launch(void* const* d_in, const int* in_sizes, int n_in,
                              void* d_out, int out_size)
{
    (void)in_sizes; (void)n_in; (void)out_size;
    const float* x  = (const float*)d_in[0];
    const float* WQ = (const float*)d_in[1];
    const float* WK = (const float*)d_in[2];
    const float* WV = (const float*)d_in[3];
    float* out = (float*)d_out;

    cudaFuncSetAttribute(tc_gemm_qkv,    cudaFuncAttributeMaxDynamicSharedMemorySize, SMEM_TOTAL);
    cudaFuncSetAttribute(tc_gemm_scores, cudaFuncAttributeMaxDynamicSharedMemorySize, SMEM_TOTAL);
    cudaFuncSetAttribute(tc_gemm_pv,     cudaFuncAttributeMaxDynamicSharedMemorySize, SMEM_TOTAL);

    const float scale = 1.0f / sqrtf((float)DM);

    // 1) fp32 -> bf16 hi/lo conversions
    convert_x_kernel<<<(MTOT * DM / 4 + 255) / 256, 256>>>(x);
    convert_w_kernel<<<(3 * DM * DM + 255) / 256, 256>>>(WQ, WK, WV);

    // 2) QKV projections (tensor cores), fused across z
    {
        dim3 grid(DM / 256, MTOT / 128, 3);       // (2, 128, 3)
        tc_gemm_qkv<<<grid, 256, SMEM_TOTAL>>>();
    }

    // 3) Scores = (Q K^T) * scale  (fp32 out)
    {
        dim3 grid(SEQ / 256, SEQ / 128, BATCH);   // (8, 16, 8)
        tc_gemm_scores<<<grid, 256, SMEM_TOTAL>>>(scale);
    }

    // 4) Softmax -> bf16 hi/lo probabilities
    softmax_kernel<<<BATCH * SEQ, 256>>>();

    // 5) Out = P V  (fp32 out)
    {
        dim3 grid(DM / 256, SEQ / 128, BATCH);    // (2, 16, 8)
        tc_gemm_pv<<<grid, 256, SMEM_TOTAL>>>(out);
    }
}

// round 15
// speedup vs baseline: 1.0071x; 1.0071x over previous
#include <cuda_runtime.h>
#include <cuda_bf16.h>
#include <stdint.h>
#include <math.h>

// ============================================================================
// Problem constants
// ============================================================================
#define BATCH 8
#define SEQ   2048
#define DM    512
#define MTOT  (BATCH * SEQ)   // 16384

// ============================================================================
// Device global scratch (bf16 hi/lo pairs + fp32 scores)
// ============================================================================
__device__ __nv_bfloat16 g_xh[MTOT * DM],  g_xl[MTOT * DM];
__device__ __nv_bfloat16 g_Wth[3][DM * DM], g_Wtl[3][DM * DM];   // transposed W: [n][k]
__device__ __nv_bfloat16 g_Qh[MTOT * DM],  g_Ql[MTOT * DM];
__device__ __nv_bfloat16 g_Kh[MTOT * DM],  g_Kl[MTOT * DM];
__device__ __nv_bfloat16 g_Vth[MTOT * DM], g_Vtl[MTOT * DM];     // transposed V: [b][d][s]
__device__ float         g_S [(size_t)BATCH * SEQ * SEQ];
__device__ __nv_bfloat16 g_Ph[(size_t)BATCH * SEQ * SEQ];
__device__ __nv_bfloat16 g_Pl[(size_t)BATCH * SEQ * SEQ];

// ============================================================================
// PTX helpers (sm_80-level: ldmatrix / mma.sync / cp.async — no 'a' features)
// ============================================================================
__device__ __forceinline__ uint32_t smem_to_u32(const void* p) {
    uint32_t a;
    asm("{ .reg .u64 t; cvta.to.shared.u64 t, %1; cvt.u32.u64 %0, t; }"
        : "=r"(a) : "l"(p));
    return a;
}

__device__ __forceinline__ void cp_async16(uint32_t dst, const void* src) {
    asm volatile("cp.async.cg.shared.global [%0], [%1], 16;"
                 :: "r"(dst), "l"(__cvta_generic_to_global(src)));
}
#define CP_COMMIT() asm volatile("cp.async.commit_group;" ::: "memory")
#define CP_WAIT(n)  asm volatile("cp.async.wait_group %0;" :: "n"(n) : "memory")

__device__ __forceinline__ void ldsm4(uint32_t* r, uint32_t addr) {
    asm volatile("ldmatrix.sync.aligned.m8n8.x4.shared.b16 {%0,%1,%2,%3}, [%4];"
                 : "=r"(r[0]), "=r"(r[1]), "=r"(r[2]), "=r"(r[3]) : "r"(addr));
}

__device__ __forceinline__ void mma_bf16(float* c, const uint32_t* a,
                                         uint32_t b0, uint32_t b1) {
    asm volatile(
        "mma.sync.aligned.m16n8k16.row.col.f32.bf16.bf16.f32 "
        "{%0,%1,%2,%3}, {%4,%5,%6,%7}, {%8,%9}, {%0,%1,%2,%3};"
        : "+f"(c[0]), "+f"(c[1]), "+f"(c[2]), "+f"(c[3])
        : "r"(a[0]), "r"(a[1]), "r"(a[2]), "r"(a[3]), "r"(b0), "r"(b1));
}

__device__ __forceinline__ void split_f32(float v, __nv_bfloat16& h, __nv_bfloat16& l) {
    h = __float2bfloat16(v);
    l = __float2bfloat16(v - __bfloat162float(h));
}

// ============================================================================
// SMEM: CTA tile 128(M) x 128(N), BK=32. Per stage: Ah, Al, Bh, Bl
// (each 128x32 bf16, rows padded to 80 B — conflict-free for ldmatrix).
// 2 stages per CTA, 2 CTAs per SM (co-residency is the point: the two CTAs
// run anti-phased so one CTA's LDSM/sync/epilogue bubbles are covered by the
// other's MMA stream).
// ============================================================================
#define PADB      80
#define TILE_T    (128 * PADB)                 // 10240 B per tile
#define STAGE_SM  (4 * TILE_T)                 // 40960 B
#define NSTAGE    2
#define SMEM_TOTAL (NSTAGE * STAGE_SM)         // 81920 B per CTA

// ============================================================================
// Core GEMM tile body: C = A * B^T  (A[M][K], B[N][K], K-contiguous),
// 3-term bf16 split on mma.sync tensor cores.
// 4 warps: 2(M) x 2(N); warp tile 64x64; per-thread acc[4][8][4].
//   EPI 0: write bf16 hi/lo row-major (out0/out1, ldC)
//   EPI 1: write bf16 hi/lo transposed (Vt[b][n][s]; batch derived from m row)
//   EPI 2: write fp32 row-major scaled by alpha
// ============================================================================
template <int EPI>
__device__ __forceinline__ void gemm_body(
    const __nv_bfloat16* __restrict__ Ah, const __nv_bfloat16* __restrict__ Al,
    const __nv_bfloat16* __restrict__ Bh, const __nv_bfloat16* __restrict__ Bl,
    void* out0, void* out1, int K, long ldA, long ldB, int ldC, float alpha)
{
    extern __shared__ char smem[];
    const uint32_t sb = smem_to_u32(smem);
    const int tid  = threadIdx.x;          // 0..127
    const int wid  = tid >> 5;             // 0..3
    const int lane = tid & 31;
    const int rowBlock = blockIdx.y * 128;
    const int colBlock = blockIdx.x * 128;
    const int wm = (wid >> 1) * 64;        // warp M offset (2 warps in M)
    const int wn = (wid & 1) * 64;         // warp N offset (2 warps in N)

    float acc[4][8][4];
#pragma unroll
    for (int mt = 0; mt < 4; mt++)
#pragma unroll
        for (int nt = 0; nt < 8; nt++)
#pragma unroll
            for (int e = 0; e < 4; e++) acc[mt][nt][e] = 0.0f;

    const __nv_bfloat16* srcA_h = Ah + (long)rowBlock * ldA;
    const __nv_bfloat16* srcA_l = Al + (long)rowBlock * ldA;
    const __nv_bfloat16* srcB_h = Bh + (long)colBlock * ldB;
    const __nv_bfloat16* srcB_l = Bl + (long)colBlock * ldB;

    // Staging: each tile = 512 16B-chunks; 128 threads -> 4 chunks/thread/tile.
    auto prefetch = [&](int chunk, int stage) {
        const long k0 = (long)chunk * 32;
        const uint32_t s0 = sb + stage * STAGE_SM;
#pragma unroll
        for (int j = 0; j < 4; j++) {
            const int t = tid + j * 128;
            const int r = t >> 2, c = t & 3;
            const uint32_t d = r * PADB + c * 16;
            cp_async16(s0 + d,              srcA_h + (long)r * ldA + k0 + c * 8);
            cp_async16(s0 + TILE_T + d,     srcA_l + (long)r * ldA + k0 + c * 8);
            cp_async16(s0 + 2 * TILE_T + d, srcB_h + (long)r * ldB + k0 + c * 8);
            cp_async16(s0 + 3 * TILE_T + d, srcB_l + (long)r * ldB + k0 + c * 8);
        }
        CP_COMMIT();
    };

    const int NIT = K / 32;
    prefetch(0, 0);

    // ldmatrix address components within a stage.
    // A x4: lanes 0-15 -> rows m0..15 @ k0; lanes 16-31 -> same rows @ k8.
    const uint32_t aRow = (uint32_t)(wm + (lane & 15)) * PADB + ((lane >> 4) * 16);
    // B x4: lanes 0-7: n0-7@k0, 8-15: n0-7@k8, 16-23: n8-15@k0, 24-31: n8-15@k8.
    const uint32_t bRow = (uint32_t)(wn + ((lane >> 4) << 3) + (lane & 7)) * PADB
                        + (((lane >> 3) & 1) * 16);

    for (int i = 0; i < NIT; i++) {
        CP_WAIT(0);
        __syncthreads();
        // Prefetch chunk i+1 into the opposite stage; its readers (iter i-1)
        // all passed the barrier above. The load flies during this iteration's
        // compute and is drained by CP_WAIT(0) at the top of iteration i+1.
        if (i + 1 < NIT) prefetch(i + 1, (i + 1) & 1);

        const uint32_t s0 = sb + (i & 1) * STAGE_SM;
        const uint32_t aBaseH = s0 + aRow;
        const uint32_t aBaseL = s0 + TILE_T + aRow;
        const uint32_t bBaseH = s0 + 2 * TILE_T + bRow;
        const uint32_t bBaseL = s0 + 3 * TILE_T + bRow;

#pragma unroll
        for (int ks = 0; ks < 2; ks++) {
            const uint32_t ko = ks * 32;            // 16 bf16 = 32 B
            uint32_t ah[4][4], al[4][4], bh[4][4], bl[4][4];
#pragma unroll
            for (int mt = 0; mt < 4; mt++) {
                ldsm4(ah[mt], aBaseH + mt * (16 * PADB) + ko);
                ldsm4(al[mt], aBaseL + mt * (16 * PADB) + ko);
            }
#pragma unroll
            for (int np = 0; np < 4; np++) {
                ldsm4(bh[np], bBaseH + np * (16 * PADB) + ko);
                ldsm4(bl[np], bBaseL + np * (16 * PADB) + ko);
            }
#pragma unroll
            for (int mt = 0; mt < 4; mt++) {
#pragma unroll
                for (int np = 0; np < 4; np++) {
                    mma_bf16(acc[mt][2 * np + 0], ah[mt], bh[np][0], bh[np][1]);
                    mma_bf16(acc[mt][2 * np + 1], ah[mt], bh[np][2], bh[np][3]);
                    mma_bf16(acc[mt][2 * np + 0], ah[mt], bl[np][0], bl[np][1]);
                    mma_bf16(acc[mt][2 * np + 1], ah[mt], bl[np][2], bl[np][3]);
                    mma_bf16(acc[mt][2 * np + 0], al[mt], bh[np][0], bh[np][1]);
                    mma_bf16(acc[mt][2 * np + 1], al[mt], bh[np][2], bh[np][3]);
                }
            }
        }
    }

    // ------------------------------------------------------------------ epilogue
    const int mBase = rowBlock + wm + (lane >> 2);
    const int nBase = colBlock + wn + 2 * (lane & 3);
#pragma unroll
    for (int mt = 0; mt < 4; mt++) {
#pragma unroll
        for (int nt = 0; nt < 8; nt++) {
            const int m0 = mBase + mt * 16;
            const int n  = nBase + nt * 8;
            const float v00 = acc[mt][nt][0], v01 = acc[mt][nt][1];
            const float v10 = acc[mt][nt][2], v11 = acc[mt][nt][3];

            if (EPI == 2) {
                float* C = (float*)out0;
                *(float2*)(C + (long)m0 * ldC + n)       = make_float2(v00 * alpha, v01 * alpha);
                *(float2*)(C + (long)(m0 + 8) * ldC + n) = make_float2(v10 * alpha, v11 * alpha);
            } else if (EPI == 0) {
                __nv_bfloat16* H = (__nv_bfloat16*)out0;
                __nv_bfloat16* L = (__nv_bfloat16*)out1;
                __nv_bfloat16 h0, l0, h1, l1;
                split_f32(v00, h0, l0); split_f32(v01, h1, l1);
                *(__nv_bfloat162*)(H + (long)m0 * ldC + n) = __nv_bfloat162(h0, h1);
                *(__nv_bfloat162*)(L + (long)m0 * ldC + n) = __nv_bfloat162(l0, l1);
                split_f32(v10, h0, l0); split_f32(v11, h1, l1);
                *(__nv_bfloat162*)(H + (long)(m0 + 8) * ldC + n) = __nv_bfloat162(h0, h1);
                *(__nv_bfloat162*)(L + (long)(m0 + 8) * ldC + n) = __nv_bfloat162(l0, l1);
            } else {  // EPI == 1: transposed store Vt[b][n][s]
                __nv_bfloat16* H = (__nv_bfloat16*)out0;
                __nv_bfloat16* L = (__nv_bfloat16*)out1;
#pragma unroll
                for (int rr = 0; rr < 2; rr++) {
                    const int m = m0 + rr * 8;
                    const int bb = m >> 11;
                    const int s  = m & 2047;
                    const float va = (rr == 0) ? v00 : v10;
                    const float vb = (rr == 0) ? v01 : v11;
                    __nv_bfloat16 h, l;
                    split_f32(va, h, l);
                    H[((long)bb * DM + n) * SEQ + s] = h;
                    L[((long)bb * DM + n) * SEQ + s] = l;
                    split_f32(vb, h, l);
                    H[((long)bb * DM + n + 1) * SEQ + s] = h;
                    L[((long)bb * DM + n + 1) * SEQ + s] = l;
                }
            }
        }
    }
}

// ---------------------------------------------------------------------------
// GEMM kernels (128 threads, 2 CTAs/SM)
// ---------------------------------------------------------------------------
__global__ __launch_bounds__(128, 2) void tc_gemm_qkv() {
    const int z = blockIdx.z;
    const __nv_bfloat16* Bh = g_Wth[z];
    const __nv_bfloat16* Bl = g_Wtl[z];
    if (z == 2) {
        gemm_body<1>(g_xh, g_xl, Bh, Bl, g_Vth, g_Vtl, DM, DM, DM, 0, 1.0f);
    } else if (z == 1) {
        gemm_body<0>(g_xh, g_xl, Bh, Bl, g_Kh, g_Kl, DM, DM, DM, DM, 1.0f);
    } else {
        gemm_body<0>(g_xh, g_xl, Bh, Bl, g_Qh, g_Ql, DM, DM, DM, DM, 1.0f);
    }
}

__global__ __launch_bounds__(128, 2) void tc_gemm_scores(float alpha) {
    const long z = blockIdx.z;
    const long sQ = (long)SEQ * DM;
    gemm_body<2>(g_Qh + z * sQ, g_Ql + z * sQ, g_Kh + z * sQ, g_Kl + z * sQ,
                 g_S + z * (long)SEQ * SEQ, nullptr, DM, DM, DM, SEQ, alpha);
}

__global__ __launch_bounds__(128, 2) void tc_gemm_pv(float* out) {
    const long z = blockIdx.z;
    gemm_body<2>(g_Ph + z * (long)SEQ * SEQ, g_Pl + z * (long)SEQ * SEQ,
                 g_Vth + z * (long)DM * SEQ, g_Vtl + z * (long)DM * SEQ,
                 out + z * (long)SEQ * DM, nullptr, SEQ, SEQ, SEQ, DM, 1.0f);
}

// ---------------------------------------------------------------------------
// Conversion kernels
// ---------------------------------------------------------------------------
__global__ __launch_bounds__(256) void convert_x_kernel(const float* __restrict__ x) {
    const long i4 = (long)(blockIdx.x * 256 + threadIdx.x) * 4;
    if (i4 >= (long)MTOT * DM) return;
    float4 v = *(const float4*)(x + i4);
    __nv_bfloat16 h0, l0, h1, l1, h2, l2, h3, l3;
    split_f32(v.x, h0, l0); split_f32(v.y, h1, l1);
    split_f32(v.z, h2, l2); split_f32(v.w, h3, l3);
    *(__nv_bfloat162*)(g_xh + i4)     = __nv_bfloat162(h0, h1);
    *(__nv_bfloat162*)(g_xh + i4 + 2) = __nv_bfloat162(h2, h3);
    *(__nv_bfloat162*)(g_xl + i4)     = __nv_bfloat162(l0, l1);
    *(__nv_bfloat162*)(g_xl + i4 + 2) = __nv_bfloat162(l2, l3);
}

__global__ __launch_bounds__(256) void convert_w_kernel(
    const float* __restrict__ WQ, const float* __restrict__ WK,
    const float* __restrict__ WV)
{
    const int idx = blockIdx.x * 256 + threadIdx.x;
    if (idx >= 3 * DM * DM) return;
    const int w = idx / (DM * DM);
    const int rem = idx - w * DM * DM;
    const int k = rem / DM, n = rem % DM;
    const float* src = (w == 0) ? WQ : (w == 1) ? WK : WV;
    __nv_bfloat16 h, l;
    split_f32(src[k * DM + n], h, l);
    g_Wth[w][n * DM + k] = h;      // transposed: [n][k]
    g_Wtl[w][n * DM + k] = l;
}

// ---------------------------------------------------------------------------
// Softmax: fp32 scores row -> bf16 hi/lo probability row
// ---------------------------------------------------------------------------
__global__ __launch_bounds__(256) void softmax_kernel() {
    const size_t rowoff = (size_t)blockIdx.x * SEQ;
    const float* row = g_S + rowoff;
    const int tid = threadIdx.x;

    float4 v[2];
    v[0] = *(const float4*)(row + tid * 4);
    v[1] = *(const float4*)(row + 1024 + tid * 4);

    __shared__ float red[8];

    float m = fmaxf(fmaxf(fmaxf(v[0].x, v[0].y), fmaxf(v[0].z, v[0].w)),
                    fmaxf(fmaxf(v[1].x, v[1].y), fmaxf(v[1].z, v[1].w)));
#pragma unroll
    for (int o = 16; o > 0; o >>= 1) m = fmaxf(m, __shfl_xor_sync(0xffffffffu, m, o));
    if ((tid & 31) == 0) red[tid >> 5] = m;
    __syncthreads();
    if (tid < 8) {
        float t = red[tid];
#pragma unroll
        for (int o = 4; o > 0; o >>= 1) t = fmaxf(t, __shfl_xor_sync(0xffu, t, o));
        if (tid == 0) red[0] = t;
    }
    __syncthreads();
    m = red[0];
    __syncthreads();

    float s = 0.0f;
#pragma unroll
    for (int i = 0; i < 2; i++) {
        v[i].x = expf(v[i].x - m); s += v[i].x;
        v[i].y = expf(v[i].y - m); s += v[i].y;
        v[i].z = expf(v[i].z - m); s += v[i].z;
        v[i].w = expf(v[i].w - m); s += v[i].w;
    }
#pragma unroll
    for (int o = 16; o > 0; o >>= 1) s += __shfl_xor_sync(0xffffffffu, s, o);
    if ((tid & 31) == 0) red[tid >> 5] = s;
    __syncthreads();
    if (tid < 8) {
        float t = red[tid];
#pragma unroll
        for (int o = 4; o > 0; o >>= 1) t += __shfl_xor_sync(0xffu, t, o);
        if (tid == 0) red[0] = t;
    }
    __syncthreads();
    const float inv = 1.0f / red[0];

    __nv_bfloat16* Ph = g_Ph + rowoff;
    __nv_bfloat16* Pl = g_Pl + rowoff;
#pragma unroll
    for (int i = 0; i < 2; i++) {
        const int base = i * 1024 + tid * 4;
        __nv_bfloat16 h0, l0, h1, l1, h2, l2, h3, l3;
        split_f32(v[i].x * inv, h0, l0);
        split_f32(v[i].y * inv, h1, l1);
        split_f32(v[i].z * inv, h2, l2);
        split_f32(v[i].w * inv, h3, l3);
        *(__nv_bfloat162*)(Ph + base)     = __nv_bfloat162(h0, h1);
        *(__nv_bfloat162*)(Ph + base + 2) = __nv_bfloat162(h2, h3);
        *(__nv_bfloat162*)(Pl + base)     = __nv_bfloat162(l0, l1);
        *(__nv_bfloat162*)(Pl + base + 2) = __nv_bfloat162(l2, l3);
    }
}

// ---------------------------------------------------------------------------
extern "C" void kernel_launch(void* const* d_in, const int* in_sizes, int n_in,
                              void* d_out, int out_size)
{
    (void)in_sizes; (void)n_in; (void)out_size;
    const float* x  = (const float*)d_in[0];
    const float* WQ = (const float*)d_in[1];
    const float* WK = (const float*)d_in[2];
    const float* WV = (const float*)d_in[3];
    float* out = (float*)d_out;

    cudaFuncSetAttribute(tc_gemm_qkv,    cudaFuncAttributeMaxDynamicSharedMemorySize, SMEM_TOTAL);
    cudaFuncSetAttribute(tc_gemm_scores, cudaFuncAttributeMaxDynamicSharedMemorySize, SMEM_TOTAL);
    cudaFuncSetAttribute(tc_gemm_pv,     cudaFuncAttributeMaxDynamicSharedMemorySize, SMEM_TOTAL);

    const float scale = 1.0f / sqrtf((float)DM);

    // 1) fp32 -> bf16 hi/lo conversions
    convert_x_kernel<<<(MTOT * DM / 4 + 255) / 256, 256>>>(x);
    convert_w_kernel<<<(3 * DM * DM + 255) / 256, 256>>>(WQ, WK, WV);

    // 2) QKV projections (tensor cores), fused across z
    {
        dim3 grid(DM / 128, MTOT / 128, 3);       // (4, 128, 3)
        tc_gemm_qkv<<<grid, 128, SMEM_TOTAL>>>();
    }

    // 3) Scores = (Q K^T) * scale  (fp32 out)
    {
        dim3 grid(SEQ / 128, SEQ / 128, BATCH);   // (16, 16, 8)
        tc_gemm_scores<<<grid, 128, SMEM_TOTAL>>>(scale);
    }

    // 4) Softmax -> bf16 hi/lo probabilities
    softmax_kernel<<<BATCH * SEQ, 256>>>();

    // 5) Out = P V  (fp32 out)
    {
        dim3 grid(DM / 128, SEQ / 128, BATCH);    // (4, 16, 8)
        tc_gemm_pv<<<grid, 128, SMEM_TOTAL>>>(out);
    }
}

// round 17
// speedup vs baseline: 1.0252x; 1.0180x over previous
#include <cuda_runtime.h>
#include <cuda_bf16.h>
#include <stdint.h>
#include <math.h>

// ============================================================================
// Problem constants
// ============================================================================
#define BATCH 8
#define SEQ   2048
#define DM    512
#define MTOT  (BATCH * SEQ)   // 16384

// ============================================================================
// Device global scratch (bf16 hi/lo pairs + fp32 scores)
// ============================================================================
__device__ __nv_bfloat16 g_xh[MTOT * DM],  g_xl[MTOT * DM];
__device__ __nv_bfloat16 g_Wth[3][DM * DM], g_Wtl[3][DM * DM];   // transposed W: [n][k]
__device__ __nv_bfloat16 g_Qh[MTOT * DM],  g_Ql[MTOT * DM];
__device__ __nv_bfloat16 g_Kh[MTOT * DM],  g_Kl[MTOT * DM];
__device__ __nv_bfloat16 g_Vth[MTOT * DM], g_Vtl[MTOT * DM];     // transposed V: [b][d][s]
__device__ float         g_S [(size_t)BATCH * SEQ * SEQ];
__device__ __nv_bfloat16 g_Ph[(size_t)BATCH * SEQ * SEQ];
__device__ __nv_bfloat16 g_Pl[(size_t)BATCH * SEQ * SEQ];

// ============================================================================
// PTX helpers (sm_80-level: ldmatrix / mma.sync / cp.async — no 'a' features)
// ============================================================================
__device__ __forceinline__ uint32_t smem_to_u32(const void* p) {
    uint32_t a;
    asm("{ .reg .u64 t; cvta.to.shared.u64 t, %1; cvt.u32.u64 %0, t; }"
        : "=r"(a) : "l"(p));
    return a;
}

__device__ __forceinline__ void cp_async16(uint32_t dst, const void* src) {
    asm volatile("cp.async.cg.shared.global [%0], [%1], 16;"
                 :: "r"(dst), "l"(__cvta_generic_to_global(src)));
}
#define CP_COMMIT() asm volatile("cp.async.commit_group;" ::: "memory")
#define CP_WAIT(n)  asm volatile("cp.async.wait_group %0;" :: "n"(n) : "memory")

__device__ __forceinline__ void ldsm4(uint32_t* r, uint32_t addr) {
    asm volatile("ldmatrix.sync.aligned.m8n8.x4.shared.b16 {%0,%1,%2,%3}, [%4];"
                 : "=r"(r[0]), "=r"(r[1]), "=r"(r[2]), "=r"(r[3]) : "r"(addr));
}

__device__ __forceinline__ void mma_bf16(float* c, const uint32_t* a,
                                         uint32_t b0, uint32_t b1) {
    asm volatile(
        "mma.sync.aligned.m16n8k16.row.col.f32.bf16.bf16.f32 "
        "{%0,%1,%2,%3}, {%4,%5,%6,%7}, {%8,%9}, {%0,%1,%2,%3};"
        : "+f"(c[0]), "+f"(c[1]), "+f"(c[2]), "+f"(c[3])
        : "r"(a[0]), "r"(a[1]), "r"(a[2]), "r"(a[3]), "r"(b0), "r"(b1));
}

__device__ __forceinline__ void split_f32(float v, __nv_bfloat16& h, __nv_bfloat16& l) {
    h = __float2bfloat16(v);
    l = __float2bfloat16(v - __bfloat162float(h));
}

// ============================================================================
// SMEM: CTA tile 128(M) x 256(N), BK=32. Per stage: Ah, Al (128x32 each),
// Bh, Bl (256x32 each). Rows padded to 80 B (conflict-free for ldmatrix).
// 3 stages, single __syncthreads per iteration.
// ============================================================================
#define PADB      80
#define TILE_A    (128 * PADB)                 // 10240 B
#define TILE_B    (256 * PADB)                 // 20480 B
#define STAGE_SM  (2 * TILE_A + 2 * TILE_B)    // 61440 B
#define NSTAGE    3
#define SMEM_TOTAL (NSTAGE * STAGE_SM)         // 184320 B

// ============================================================================
// Core GEMM tile body: C = A * B^T  (A[M][K], B[N][K], K-contiguous),
// 3-term bf16 split on mma.sync tensor cores.
// 8 warps: 2(M) x 4(N); warp tile 64x64; per-thread acc[4][8][4].
// MMA issue is TERM-MAJOR: the three split terms are three passes over the
// full mt x np tile, so same-accumulator reuse distance is 32 independent
// MMAs (covers HMMA acc-RAW latency) instead of 2.
//   EPI 0: write bf16 hi/lo row-major (out0/out1, ldC)
//   EPI 1: write bf16 hi/lo transposed (Vt[b][n][s]; batch derived from m row)
//   EPI 2: write fp32 row-major scaled by alpha
// ============================================================================
template <int EPI>
__device__ __forceinline__ void gemm_body(
    const __nv_bfloat16* __restrict__ Ah, const __nv_bfloat16* __restrict__ Al,
    const __nv_bfloat16* __restrict__ Bh, const __nv_bfloat16* __restrict__ Bl,
    void* out0, void* out1, int K, long ldA, long ldB, int ldC, float alpha)
{
    extern __shared__ char smem[];
    const uint32_t sb = smem_to_u32(smem);
    const int tid  = threadIdx.x;
    const int wid  = tid >> 5;
    const int lane = tid & 31;
    const int rowBlock = blockIdx.y * 128;
    const int colBlock = blockIdx.x * 256;
    const int wm = (wid >> 2) * 64;   // warp M offset (2 warps in M)
    const int wn = (wid & 3) * 64;    // warp N offset (4 warps in N)

    float acc[4][8][4];
#pragma unroll
    for (int mt = 0; mt < 4; mt++)
#pragma unroll
        for (int nt = 0; nt < 8; nt++)
#pragma unroll
            for (int e = 0; e < 4; e++) acc[mt][nt][e] = 0.0f;

    const __nv_bfloat16* srcA_h = Ah + (long)rowBlock * ldA;
    const __nv_bfloat16* srcA_l = Al + (long)rowBlock * ldA;
    const __nv_bfloat16* srcB_h = Bh + (long)colBlock * ldB;
    const __nv_bfloat16* srcB_l = Bl + (long)colBlock * ldB;

    // Staging: A tiles 512 chunks (2/thread), B tiles 1024 chunks (4/thread).
    auto prefetch = [&](int chunk, int stage) {
        const long k0 = (long)chunk * 32;
        const uint32_t s0 = sb + stage * STAGE_SM;
#pragma unroll
        for (int j = 0; j < 2; j++) {
            const int t = tid + j * 256;
            const int r = t >> 2, c = t & 3;
            cp_async16(s0 + r * PADB + c * 16,          srcA_h + (long)r * ldA + k0 + c * 8);
            cp_async16(s0 + TILE_A + r * PADB + c * 16, srcA_l + (long)r * ldA + k0 + c * 8);
        }
#pragma unroll
        for (int j = 0; j < 4; j++) {
            const int t = tid + j * 256;
            const int r = t >> 2, c = t & 3;
            cp_async16(s0 + 2 * TILE_A + r * PADB + c * 16,
                       srcB_h + (long)r * ldB + k0 + c * 8);
            cp_async16(s0 + 2 * TILE_A + TILE_B + r * PADB + c * 16,
                       srcB_l + (long)r * ldB + k0 + c * 8);
        }
        CP_COMMIT();
    };

    const int NIT = K / 32;
    prefetch(0, 0);
    prefetch(1, 1);

    // ldmatrix address components within a stage.
    // A x4: lanes 0-15 -> rows m0..15 @ k0; lanes 16-31 -> same rows @ k8.
    const uint32_t aRow = (uint32_t)(wm + (lane & 15)) * PADB + ((lane >> 4) * 16);
    // B x4: lanes 0-7: n0-7@k0, 8-15: n0-7@k8, 16-23: n8-15@k0, 24-31: n8-15@k8.
    const uint32_t bRow = (uint32_t)(wn + ((lane >> 4) << 3) + (lane & 7)) * PADB
                        + (((lane >> 3) & 1) * 16);

    int stage = 0;       // stage holding chunk i
    int pstage = 2;      // stage to receive chunk i+2 (== (i+2)%3)
    for (int i = 0; i < NIT; i++) {
        if (i + 1 < NIT) { CP_WAIT(1); } else { CP_WAIT(0); }
        __syncthreads();

        const uint32_t s0 = sb + stage * STAGE_SM;
        const uint32_t aBaseH = s0 + aRow;
        const uint32_t aBaseL = s0 + TILE_A + aRow;
        const uint32_t bBaseH = s0 + 2 * TILE_A + bRow;
        const uint32_t bBaseL = s0 + 2 * TILE_A + TILE_B + bRow;

#pragma unroll
        for (int ks = 0; ks < 2; ks++) {
            const uint32_t ko = ks * 32;            // 16 bf16 = 32 B
            uint32_t ah[4][4], al[4][4], bh[4][4], bl[4][4];
#pragma unroll
            for (int mt = 0; mt < 4; mt++) {
                ldsm4(ah[mt], aBaseH + mt * (16 * PADB) + ko);
                ldsm4(al[mt], aBaseL + mt * (16 * PADB) + ko);
            }
#pragma unroll
            for (int np = 0; np < 4; np++) {
                ldsm4(bh[np], bBaseH + np * (16 * PADB) + ko);
                ldsm4(bl[np], bBaseL + np * (16 * PADB) + ko);
            }
            // Term-major: three passes over the whole warp tile. Any given
            // accumulator is touched once per pass -> reuse distance 32.
#pragma unroll
            for (int mt = 0; mt < 4; mt++)
#pragma unroll
                for (int np = 0; np < 4; np++) {
                    mma_bf16(acc[mt][2 * np + 0], ah[mt], bh[np][0], bh[np][1]);
                    mma_bf16(acc[mt][2 * np + 1], ah[mt], bh[np][2], bh[np][3]);
                }
#pragma unroll
            for (int mt = 0; mt < 4; mt++)
#pragma unroll
                for (int np = 0; np < 4; np++) {
                    mma_bf16(acc[mt][2 * np + 0], ah[mt], bl[np][0], bl[np][1]);
                    mma_bf16(acc[mt][2 * np + 1], ah[mt], bl[np][2], bl[np][3]);
                }
#pragma unroll
            for (int mt = 0; mt < 4; mt++)
#pragma unroll
                for (int np = 0; np < 4; np++) {
                    mma_bf16(acc[mt][2 * np + 0], al[mt], bh[np][0], bh[np][1]);
                    mma_bf16(acc[mt][2 * np + 1], al[mt], bh[np][2], bh[np][3]);
                }
        }

        // Chunk i+2 goes into stage (i+2)%3 — last read at iter i-1, so the
        // barrier at the top of THIS iteration made it safe to overwrite.
        if (i + 2 < NIT) prefetch(i + 2, pstage);
        stage  = (stage  == NSTAGE - 1) ? 0 : stage + 1;
        pstage = (pstage == NSTAGE - 1) ? 0 : pstage + 1;
    }

    // ------------------------------------------------------------------ epilogue
    const int mBase = rowBlock + wm + (lane >> 2);
    const int nBase = colBlock + wn + 2 * (lane & 3);
#pragma unroll
    for (int mt = 0; mt < 4; mt++) {
#pragma unroll
        for (int nt = 0; nt < 8; nt++) {
            const int m0 = mBase + mt * 16;
            const int n  = nBase + nt * 8;
            const float v00 = acc[mt][nt][0], v01 = acc[mt][nt][1];
            const float v10 = acc[mt][nt][2], v11 = acc[mt][nt][3];

            if (EPI == 2) {
                float* C = (float*)out0;
                *(float2*)(C + (long)m0 * ldC + n)       = make_float2(v00 * alpha, v01 * alpha);
                *(float2*)(C + (long)(m0 + 8) * ldC + n) = make_float2(v10 * alpha, v11 * alpha);
            } else if (EPI == 0) {
                __nv_bfloat16* H = (__nv_bfloat16*)out0;
                __nv_bfloat16* L = (__nv_bfloat16*)out1;
                __nv_bfloat16 h0, l0, h1, l1;
                split_f32(v00, h0, l0); split_f32(v01, h1, l1);
                *(__nv_bfloat162*)(H + (long)m0 * ldC + n) = __nv_bfloat162(h0, h1);
                *(__nv_bfloat162*)(L + (long)m0 * ldC + n) = __nv_bfloat162(l0, l1);
                split_f32(v10, h0, l0); split_f32(v11, h1, l1);
                *(__nv_bfloat162*)(H + (long)(m0 + 8) * ldC + n) = __nv_bfloat162(h0, h1);
                *(__nv_bfloat162*)(L + (long)(m0 + 8) * ldC + n) = __nv_bfloat162(l0, l1);
            } else {  // EPI == 1: transposed store Vt[b][n][s]
                __nv_bfloat16* H = (__nv_bfloat16*)out0;
                __nv_bfloat16* L = (__nv_bfloat16*)out1;
#pragma unroll
                for (int rr = 0; rr < 2; rr++) {
                    const int m = m0 + rr * 8;
                    const int bb = m >> 11;
                    const int s  = m & 2047;
                    const float va = (rr == 0) ? v00 : v10;
                    const float vb = (rr == 0) ? v01 : v11;
                    __nv_bfloat16 h, l;
                    split_f32(va, h, l);
                    H[((long)bb * DM + n) * SEQ + s] = h;
                    L[((long)bb * DM + n) * SEQ + s] = l;
                    split_f32(vb, h, l);
                    H[((long)bb * DM + n + 1) * SEQ + s] = h;
                    L[((long)bb * DM + n + 1) * SEQ + s] = l;
                }
            }
        }
    }
}

// ---------------------------------------------------------------------------
// GEMM kernels
// ---------------------------------------------------------------------------
__global__ __launch_bounds__(256, 1) void tc_gemm_qkv() {
    const int z = blockIdx.z;
    const __nv_bfloat16* Bh = g_Wth[z];
    const __nv_bfloat16* Bl = g_Wtl[z];
    if (z == 2) {
        gemm_body<1>(g_xh, g_xl, Bh, Bl, g_Vth, g_Vtl, DM, DM, DM, 0, 1.0f);
    } else if (z == 1) {
        gemm_body<0>(g_xh, g_xl, Bh, Bl, g_Kh, g_Kl, DM, DM, DM, DM, 1.0f);
    } else {
        gemm_body<0>(g_xh, g_xl, Bh, Bl, g_Qh, g_Ql, DM, DM, DM, DM, 1.0f);
    }
}

__global__ __launch_bounds__(256, 1) void tc_gemm_scores(float alpha) {
    const long z = blockIdx.z;
    const long sQ = (long)SEQ * DM;
    gemm_body<2>(g_Qh + z * sQ, g_Ql + z * sQ, g_Kh + z * sQ, g_Kl + z * sQ,
                 g_S + z * (long)SEQ * SEQ, nullptr, DM, DM, DM, SEQ, alpha);
}

__global__ __launch_bounds__(256, 1) void tc_gemm_pv(float* out) {
    const long z = blockIdx.z;
    gemm_body<2>(g_Ph + z * (long)SEQ * SEQ, g_Pl + z * (long)SEQ * SEQ,
                 g_Vth + z * (long)DM * SEQ, g_Vtl + z * (long)DM * SEQ,
                 out + z * (long)SEQ * DM, nullptr, SEQ, SEQ, SEQ, DM, 1.0f);
}

// ---------------------------------------------------------------------------
// Conversion kernels
// ---------------------------------------------------------------------------
__global__ __launch_bounds__(256) void convert_x_kernel(const float* __restrict__ x) {
    const long i4 = (long)(blockIdx.x * 256 + threadIdx.x) * 4;
    if (i4 >= (long)MTOT * DM) return;
    float4 v = *(const float4*)(x + i4);
    __nv_bfloat16 h0, l0, h1, l1, h2, l2, h3, l3;
    split_f32(v.x, h0, l0); split_f32(v.y, h1, l1);
    split_f32(v.z, h2, l2); split_f32(v.w, h3, l3);
    *(__nv_bfloat162*)(g_xh + i4)     = __nv_bfloat162(h0, h1);
    *(__nv_bfloat162*)(g_xh + i4 + 2) = __nv_bfloat162(h2, h3);
    *(__nv_bfloat162*)(g_xl + i4)     = __nv_bfloat162(l0, l1);
    *(__nv_bfloat162*)(g_xl + i4 + 2) = __nv_bfloat162(l2, l3);
}

__global__ __launch_bounds__(256) void convert_w_kernel(
    const float* __restrict__ WQ, const float* __restrict__ WK,
    const float* __restrict__ WV)
{
    const int idx = blockIdx.x * 256 + threadIdx.x;
    if (idx >= 3 * DM * DM) return;
    const int w = idx / (DM * DM);
    const int rem = idx - w * DM * DM;
    const int k = rem / DM, n = rem % DM;
    const float* src = (w == 0) ? WQ : (w == 1) ? WK : WV;
    __nv_bfloat16 h, l;
    split_f32(src[k * DM + n], h, l);
    g_Wth[w][n * DM + k] = h;      // transposed: [n][k]
    g_Wtl[w][n * DM + k] = l;
}

// ---------------------------------------------------------------------------
// Softmax: fp32 scores row -> bf16 hi/lo probability row
// ---------------------------------------------------------------------------
__global__ __launch_bounds__(256) void softmax_kernel() {
    const size_t rowoff = (size_t)blockIdx.x * SEQ;
    const float* row = g_S + rowoff;
    const int tid = threadIdx.x;

    float4 v[2];
    v[0] = *(const float4*)(row + tid * 4);
    v[1] = *(const float4*)(row + 1024 + tid * 4);

    __shared__ float red[8];

    float m = fmaxf(fmaxf(fmaxf(v[0].x, v[0].y), fmaxf(v[0].z, v[0].w)),
                    fmaxf(fmaxf(v[1].x, v[1].y), fmaxf(v[1].z, v[1].w)));
#pragma unroll
    for (int o = 16; o > 0; o >>= 1) m = fmaxf(m, __shfl_xor_sync(0xffffffffu, m, o));
    if ((tid & 31) == 0) red[tid >> 5] = m;
    __syncthreads();
    if (tid < 8) {
        float t = red[tid];
#pragma unroll
        for (int o = 4; o > 0; o >>= 1) t = fmaxf(t, __shfl_xor_sync(0xffu, t, o));
        if (tid == 0) red[0] = t;
    }
    __syncthreads();
    m = red[0];
    __syncthreads();

    float s = 0.0f;
#pragma unroll
    for (int i = 0; i < 2; i++) {
        v[i].x = expf(v[i].x - m); s += v[i].x;
        v[i].y = expf(v[i].y - m); s += v[i].y;
        v[i].z = expf(v[i].z - m); s += v[i].z;
        v[i].w = expf(v[i].w - m); s += v[i].w;
    }
#pragma unroll
    for (int o = 16; o > 0; o >>= 1) s += __shfl_xor_sync(0xffffffffu, s, o);
    if ((tid & 31) == 0) red[tid >> 5] = s;
    __syncthreads();
    if (tid < 8) {
        float t = red[tid];
#pragma unroll
        for (int o = 4; o > 0; o >>= 1) t += __shfl_xor_sync(0xffu, t, o);
        if (tid == 0) red[0] = t;
    }
    __syncthreads();
    const float inv = 1.0f / red[0];

    __nv_bfloat16* Ph = g_Ph + rowoff;
    __nv_bfloat16* Pl = g_Pl + rowoff;
#pragma unroll
    for (int i = 0; i < 2; i++) {
        const int base = i * 1024 + tid * 4;
        __nv_bfloat16 h0, l0, h1, l1, h2, l2, h3, l3;
        split_f32(v[i].x * inv, h0, l0);
        split_f32(v[i].y * inv, h1, l1);
        split_f32(v[i].z * inv, h2, l2);
        split_f32(v[i].w * inv, h3, l3);
        *(__nv_bfloat162*)(Ph + base)     = __nv_bfloat162(h0, h1);
        *(__nv_bfloat162*)(Ph + base + 2) = __nv_bfloat162(h2, h3);
        *(__nv_bfloat162*)(Pl + base)     = __nv_bfloat162(l0, l1);
        *(__nv_bfloat162*)(Pl + base + 2) = __nv_bfloat162(l2, l3);
    }
}

// ---------------------------------------------------------------------------
extern "C" void kernel_launch(void* const* d_in, const int* in_sizes, int n_in,
                              void* d_out, int out_size)
{
    (void)in_sizes; (void)n_in; (void)out_size;
    const float* x  = (const float*)d_in[0];
    const float* WQ = (const float*)d_in[1];
    const float* WK = (const float*)d_in[2];
    const float* WV = (const float*)d_in[3];
    float* out = (float*)d_out;

    cudaFuncSetAttribute(tc_gemm_qkv,    cudaFuncAttributeMaxDynamicSharedMemorySize, SMEM_TOTAL);
    cudaFuncSetAttribute(tc_gemm_scores, cudaFuncAttributeMaxDynamicSharedMemorySize, SMEM_TOTAL);
    cudaFuncSetAttribute(tc_gemm_pv,     cudaFuncAttributeMaxDynamicSharedMemorySize, SMEM_TOTAL);

    const float scale = 1.0f / sqrtf((float)DM);

    // 1) fp32 -> bf16 hi/lo conversions
    convert_x_kernel<<<(MTOT * DM / 4 + 255) / 256, 256>>>(x);
    convert_w_kernel<<<(3 * DM * DM + 255) / 256, 256>>>(WQ, WK, WV);

    // 2) QKV projections (tensor cores), fused across z
    {
        dim3 grid(DM / 256, MTOT / 128, 3);       // (2, 128, 3)
        tc_gemm_qkv<<<grid, 256, SMEM_TOTAL>>>();
    }

    // 3) Scores = (Q K^T) * scale  (fp32 out)
    {
        dim3 grid(SEQ / 256, SEQ / 128, BATCH);   // (8, 16, 8)
        tc_gemm_scores<<<grid, 256, SMEM_TOTAL>>>(scale);
    }

    // 4) Softmax -> bf16 hi/lo probabilities
    softmax_kernel<<<BATCH * SEQ, 256>>>();

    // 5) Out = P V  (fp32 out)
    {
        dim3 grid(DM / 256, SEQ / 128, BATCH);    // (2, 16, 8)
        tc_gemm_pv<<<grid, 256, SMEM_TOTAL>>>(out);
    }
}